// round 1
// baseline (speedup 1.0000x reference)
#include <cuda_runtime.h>
#include <math.h>

#define N_NODES 16384
#define D 128
#define BATCH 4
#define TILE_NODES 64
#define WPRIME (0.05f/1.05f)

// ---------------- device scratch (no allocations allowed) ----------------
__device__ float g_Rm[BATCH * D * D];
__device__ int   g_rowptr[N_NODES + 1];
__device__ float g_partial[BATCH];

// ---------------- K0: zero Rm ----------------
__global__ void zero_kernel() {
    int i = blockIdx.x * blockDim.x + threadIdx.x;
    if (i < BATCH * D * D) g_Rm[i] = 0.0f;
}

// ---------------- K1: CSR row pointers (e0 is sorted ascending) ----------------
__global__ void rowptr_kernel(const int* __restrict__ e0, int E) {
    int n = blockIdx.x * blockDim.x + threadIdx.x;
    if (n > N_NODES) return;
    int lo = 0, hi = E;
    while (lo < hi) {
        int mid = (lo + hi) >> 1;
        if (e0[mid] < n) lo = mid + 1; else hi = mid;
    }
    g_rowptr[n] = lo;
}

// ---------------- K2: fused panel build + rank-14 contraction ----------------
// Rm[b] = sum_n A_n^T B_n,  A_n,B_n : [7,128] per node.
// Block: 256 threads. Per iteration: 2 nodes built (128 threads each, thread = column),
// then 14-rank outer-product update of an 8x8-per-thread 128x128 accumulator.
__global__ void __launch_bounds__(256, 2)
main_kernel(const float* __restrict__ x, const float* __restrict__ J,
            const int* __restrict__ e1arr) {
    __shared__ __align__(16) float As[14][D];
    __shared__ __align__(16) float Bs[14][D];

    const int b = blockIdx.y;
    const int tileBase = blockIdx.x * TILE_NODES;
    const int t  = threadIdx.x;
    const int g  = t >> 7;      // which of the 2 nodes this thread builds
    const int c  = t & 127;     // latent column
    const int ty = t >> 4;      // 0..15 (row tile of Rm)
    const int tx = t & 15;      // 0..15 (col tile of Rm)

    const float* xb = x + (size_t)b * N_NODES * 3;
    const float* Jb = J + (size_t)b * N_NODES * 3 * D;

    float acc[8][8];
#pragma unroll
    for (int i = 0; i < 8; i++)
#pragma unroll
        for (int j = 0; j < 8; j++) acc[i][j] = 0.0f;

    for (int it = 0; it < TILE_NODES / 2; ++it) {
        // ---- phase 1: build panels for node n (per 128-thread group) ----
        const int n = tileBase + it * 2 + g;
        const float* Jn = Jb + (size_t)(3 * n) * D + c;
        const float Jn0 = Jn[0], Jn1 = Jn[D], Jn2 = Jn[2 * D];
        const float xn0 = xb[3 * n], xn1 = xb[3 * n + 1], xn2 = xb[3 * n + 2];

        float nb0 = 0.f, nb1 = 0.f, nb2 = 0.f;
        float T0 = 0.f, T1 = 0.f, T2 = 0.f, u = 0.f;
        float deg = 0.f, s0 = 0.f, s1 = 0.f, s2 = 0.f, G = 0.f;
        float c00 = 0.f, c01 = 0.f, c02 = 0.f, c11 = 0.f, c12 = 0.f, c22 = 0.f;

        const int eBeg = g_rowptr[n], eEnd = g_rowptr[n + 1];
        for (int e = eBeg; e < eEnd; ++e) {
            const int m = e1arr[e];
            const float v0 = xn0 - xb[3 * m];
            const float v1 = xn1 - xb[3 * m + 1];
            const float v2 = xn2 - xb[3 * m + 2];
            const float* Jm = Jb + (size_t)(3 * m) * D + c;
            const float Jm0 = Jm[0], Jm1 = Jm[D], Jm2 = Jm[2 * D];
            nb0 += Jm0; nb1 += Jm1; nb2 += Jm2;
            T0 += v1 * Jm2 - v2 * Jm1;     // S(v)*Jm, row 0
            T1 += v2 * Jm0 - v0 * Jm2;     // row 1
            T2 += v0 * Jm1 - v1 * Jm0;     // row 2
            u  += v0 * Jm0 + v1 * Jm1 + v2 * Jm2;
            deg += 1.0f; s0 += v0; s1 += v1; s2 += v2;
            const float vv = v0 * v0 + v1 * v1 + v2 * v2;
            G += vv;
            c00 += vv - v0 * v0; c01 -= v0 * v1; c02 -= v0 * v2;
            c11 += vv - v1 * v1; c12 -= v1 * v2; c22 += vv - v2 * v2;
        }

        // LJ = 2(deg*Jn - sum_m Jm)
        const float LJ0 = 2.0f * (deg * Jn0 - nb0);
        const float LJ1 = 2.0f * (deg * Jn1 - nb1);
        const float LJ2 = 2.0f * (deg * Jn2 - nb2);
        // BTJ = T - S(Svec)*Jn
        const float B0 = T0 + s2 * Jn1 - s1 * Jn2;
        const float B1 = T1 - s2 * Jn0 + s0 * Jn2;
        const float B2 = T2 + s1 * Jn0 - s0 * Jn1;
        // HTJ = u - Svec^T Jn
        const float y = u - (s0 * Jn0 + s1 * Jn1 + s2 * Jn2);
        // Cholesky of C, Z = L^{-1} BTJ  =>  BTJ^T C^{-1} BTJ = Z^T Z
        const float l00 = sqrtf(c00);
        const float il00 = 1.0f / l00;
        const float l10 = c01 * il00, l20 = c02 * il00;
        const float l11 = sqrtf(c11 - l10 * l10);
        const float il11 = 1.0f / l11;
        const float l21 = (c12 - l20 * l10) * il11;
        const float l22 = sqrtf(c22 - l20 * l20 - l21 * l21);
        const float il22 = 1.0f / l22;
        const float Z0 = B0 * il00;
        const float Z1 = (B1 - l10 * Z0) * il11;
        const float Z2 = (B2 - l20 * Z0 - l21 * Z1) * il22;
        const float Ginv = (G < 1e-6f) ? 0.0f : 1.0f / G;

        const int r = g * 7;
        As[r + 0][c] = Jn0; As[r + 1][c] = Jn1; As[r + 2][c] = Jn2;
        As[r + 3][c] = Z0;  As[r + 4][c] = Z1;  As[r + 5][c] = Z2;
        As[r + 6][c] = y;
        Bs[r + 0][c] = LJ0; Bs[r + 1][c] = LJ1; Bs[r + 2][c] = LJ2;
        Bs[r + 3][c] = -Z0; Bs[r + 4][c] = -Z1; Bs[r + 5][c] = -Z2;
        Bs[r + 6][c] = -(WPRIME * Ginv) * y;
        __syncthreads();

        // ---- phase 2: rank-14 update of the 128x128 accumulator ----
#pragma unroll
        for (int k = 0; k < 14; ++k) {
            const float4 a0 = *(const float4*)&As[k][ty * 8];
            const float4 a1 = *(const float4*)&As[k][ty * 8 + 4];
            const float4 b0 = *(const float4*)&Bs[k][tx * 8];
            const float4 b1 = *(const float4*)&Bs[k][tx * 8 + 4];
            const float av[8] = {a0.x, a0.y, a0.z, a0.w, a1.x, a1.y, a1.z, a1.w};
            const float bv[8] = {b0.x, b0.y, b0.z, b0.w, b1.x, b1.y, b1.z, b1.w};
#pragma unroll
            for (int i = 0; i < 8; i++)
#pragma unroll
                for (int j = 0; j < 8; j++)
                    acc[i][j] += av[i] * bv[j];
        }
        __syncthreads();
    }

    float* Rm = g_Rm + (size_t)b * D * D;
#pragma unroll
    for (int i = 0; i < 8; i++)
#pragma unroll
        for (int j = 0; j < 8; j++)
            atomicAdd(&Rm[(ty * 8 + i) * D + (tx * 8 + j)], acc[i][j]);
}

// ---------------- block reductions (128 threads) ----------------
__device__ __forceinline__ float blockReduceSum(float v, float* red) {
#pragma unroll
    for (int off = 16; off > 0; off >>= 1) v += __shfl_down_sync(0xffffffffu, v, off);
    if ((threadIdx.x & 31) == 0) red[threadIdx.x >> 5] = v;
    __syncthreads();
    if (threadIdx.x == 0) red[0] = red[0] + red[1] + red[2] + red[3];
    __syncthreads();
    const float r = red[0];
    __syncthreads();
    return r;
}
__device__ __forceinline__ float blockReduceMin(float v, float* red) {
#pragma unroll
    for (int off = 16; off > 0; off >>= 1) v = fminf(v, __shfl_down_sync(0xffffffffu, v, off));
    if ((threadIdx.x & 31) == 0) red[threadIdx.x >> 5] = v;
    __syncthreads();
    if (threadIdx.x == 0) red[0] = fminf(fminf(red[0], red[1]), fminf(red[2], red[3]));
    __syncthreads();
    const float r = red[0];
    __syncthreads();
    return r;
}
__device__ __forceinline__ float blockReduceMax(float v, float* red) {
#pragma unroll
    for (int off = 16; off > 0; off >>= 1) v = fmaxf(v, __shfl_down_sync(0xffffffffu, v, off));
    if ((threadIdx.x & 31) == 0) red[threadIdx.x >> 5] = v;
    __syncthreads();
    if (threadIdx.x == 0) red[0] = fmaxf(fmaxf(red[0], red[1]), fmaxf(red[2], red[3]));
    __syncthreads();
    const float r = red[0];
    __syncthreads();
    return r;
}

// ---------------- K3: Householder tridiagonalization + Sturm bisection ----------------
// One block per sample, 128 threads. A lives in padded (stride-129) dynamic smem.
#define SMEM_EIG ((128 * 129 + 5 * 128 + 32) * 4)

__global__ void eigen_kernel() {
    extern __shared__ float sm[];
    float* A   = sm;                 // 128 x 129
    float* uu  = A + 128 * 129;      // 128
    float* qq  = uu + 128;           // 128
    float* dd  = qq + 128;           // 128
    float* ee  = dd + 128;           // 128
    float* e2  = ee + 128;           // 128
    float* red = e2 + 128;           // 32

    const int b = blockIdx.x;
    const int t = threadIdx.x;
    const float* R = g_Rm + (size_t)b * D * D;

    // load + symmetrize
    for (int i = 0; i < 128; i++)
        A[i * 129 + t] = 0.5f * (R[i * 128 + t] + R[t * 128 + i]);
    __syncthreads();

    // Householder reduction to tridiagonal (eigenvalues only)
    for (int k = 0; k < 126; k++) {
        const float xi = (t > k) ? A[t * 129 + k] : 0.0f;
        const float sig = blockReduceSum(xi * xi, red);
        const float x0 = A[(k + 1) * 129 + k];
        const float nrm = sqrtf(sig);
        const float alpha = (x0 >= 0.0f) ? -nrm : nrm;
        const float H = sig - alpha * x0;      // = 0.5 * u^T u
        if (t == 0) ee[k + 1] = alpha;
        const float ui = (t > k) ? (xi - ((t == k + 1) ? alpha : 0.0f)) : 0.0f;
        uu[t] = ui;
        __syncthreads();
        if (H > 1e-32f) {                       // H is block-uniform
            const float invH = 1.0f / H;
            float p = 0.0f;
            if (t > k) {
                const float* Ar = A + t * 129;
                for (int j = k + 1; j < 128; j++) p += Ar[j] * uu[j];
                p *= invH;
            }
            const float Ks = blockReduceSum(ui * p, red);
            const float Kc = Ks * 0.5f * invH;
            qq[t] = p - Kc * ui;
            __syncthreads();
            if (t > k) {
                float* Ar = A + t * 129;
                const float qi = qq[t];
                for (int j = k + 1; j < 128; j++)
                    Ar[j] -= ui * qq[j] + qi * uu[j];
            }
        }
        __syncthreads();
    }

    dd[t] = A[t * 129 + t];
    if (t == 0) { ee[0] = 0.0f; ee[127] = A[127 * 129 + 126]; }
    __syncthreads();
    e2[t] = ee[t] * ee[t];
    const float rad = fabsf(ee[t]) + ((t < 127) ? fabsf(ee[t + 1]) : 0.0f);
    const float gl = blockReduceMin(dd[t] - rad, red);
    const float gu = blockReduceMax(dd[t] + rad, red);
    __syncthreads();

    // bisection: thread t finds the t-th smallest eigenvalue
    const float pivmin = fmaxf(1e-12f * fmaxf(fabsf(gl), fabsf(gu)), 1e-36f);
    float lo = gl, hi = gu;
    for (int iter = 0; iter < 40; ++iter) {
        const float mid = 0.5f * (lo + hi);
        int cnt = 0;
        float q = dd[0] - mid;
        if (q < 0.0f) cnt++;
#pragma unroll 4
        for (int i = 1; i < 128; i++) {
            if (fabsf(q) < pivmin) q = -pivmin;
            q = dd[i] - mid - __fdividef(e2[i], q);
            if (q < 0.0f) cnt++;
        }
        if (cnt > t) hi = mid; else lo = mid;
    }
    const float lam = 0.5f * (lo + hi);
    const float v = (lam > 0.0f) ? sqrtf(lam) : 0.0f;
    const float s = blockReduceSum(v, red);
    if (t == 0) g_partial[b] = s;
}

// ---------------- K4: mean over batch ----------------
__global__ void finalize_kernel(float* out) {
    out[0] = 0.25f * (g_partial[0] + g_partial[1] + g_partial[2] + g_partial[3]);
}

// ---------------- launch ----------------
extern "C" void kernel_launch(void* const* d_in, const int* in_sizes, int n_in,
                              void* d_out, int out_size) {
    const float* x  = (const float*)d_in[0];
    const float* J  = (const float*)d_in[1];
    const int*   ei = (const int*)d_in[2];     // [2, E] int32, e0 sorted
    const int E = in_sizes[2] / 2;
    float* out = (float*)d_out;

    cudaFuncSetAttribute(eigen_kernel,
                         cudaFuncAttributeMaxDynamicSharedMemorySize, SMEM_EIG);

    zero_kernel<<<64, 1024>>>();
    rowptr_kernel<<<(N_NODES + 1 + 255) / 256, 256>>>(ei, E);

    dim3 gmain(N_NODES / TILE_NODES, BATCH);
    main_kernel<<<gmain, 256>>>(x, J, ei + E);

    eigen_kernel<<<BATCH, 128, SMEM_EIG>>>();
    finalize_kernel<<<1, 1>>>(out);
}

// round 2
// speedup vs baseline: 1.2682x; 1.2682x over previous
#include <cuda_runtime.h>
#include <math.h>
#include <stdint.h>

#define N_NODES 16384
#define D 128
#define BATCH 4
#define WPRIME (0.05f/1.05f)

// ---------------- device scratch (no allocations allowed) ----------------
__device__ float g_Rm[BATCH * D * D];
__device__ int   g_rowptr[N_NODES + 1];
__device__ float g_partial[BATCH];
// per node: rows [Z0,Z1,Z2,y, LJ0,LJ1,LJ2,gy] x 128 = 1024 floats
__device__ float g_pan[(size_t)BATCH * N_NODES * 1024];

// ---------------- K0: zero Rm ----------------
__global__ void zero_kernel() {
    int i = blockIdx.x * blockDim.x + threadIdx.x;
    if (i < BATCH * D * D) g_Rm[i] = 0.0f;
}

// ---------------- K1: CSR row pointers (e0 sorted ascending) ----------------
__global__ void rowptr_kernel(const int* __restrict__ e0, int E) {
    int n = blockIdx.x * blockDim.x + threadIdx.x;
    if (n > N_NODES) return;
    int lo = 0, hi = E;
    while (lo < hi) {
        int mid = (lo + hi) >> 1;
        if (e0[mid] < n) lo = mid + 1; else hi = mid;
    }
    g_rowptr[n] = lo;
}

// ---------------- K2a: build per-node panels (gather, memory-bound) ----------------
__global__ void __launch_bounds__(256)
build_kernel(const float* __restrict__ x, const float* __restrict__ J,
             const int* __restrict__ e1arr) {
    const int b = blockIdx.y;
    const int n = blockIdx.x * 2 + (threadIdx.x >> 7);
    const int c = threadIdx.x & 127;

    const float* xb = x + (size_t)b * N_NODES * 3;
    const float* Jb = J + (size_t)b * N_NODES * 3 * D;

    const float* Jn = Jb + (size_t)(3 * n) * D + c;
    const float Jn0 = Jn[0], Jn1 = Jn[D], Jn2 = Jn[2 * D];
    const float xn0 = xb[3 * n], xn1 = xb[3 * n + 1], xn2 = xb[3 * n + 2];

    float nb0 = 0.f, nb1 = 0.f, nb2 = 0.f;
    float T0 = 0.f, T1 = 0.f, T2 = 0.f, u = 0.f;
    float deg = 0.f, s0 = 0.f, s1 = 0.f, s2 = 0.f, G = 0.f;
    float c00 = 0.f, c01 = 0.f, c02 = 0.f, c11 = 0.f, c12 = 0.f, c22 = 0.f;

    const int eBeg = g_rowptr[n], eEnd = g_rowptr[n + 1];
#pragma unroll 2
    for (int e = eBeg; e < eEnd; ++e) {
        const int m = e1arr[e];
        const float v0 = xn0 - xb[3 * m];
        const float v1 = xn1 - xb[3 * m + 1];
        const float v2 = xn2 - xb[3 * m + 2];
        const float* Jm = Jb + (size_t)(3 * m) * D + c;
        const float Jm0 = Jm[0], Jm1 = Jm[D], Jm2 = Jm[2 * D];
        nb0 += Jm0; nb1 += Jm1; nb2 += Jm2;
        T0 += v1 * Jm2 - v2 * Jm1;
        T1 += v2 * Jm0 - v0 * Jm2;
        T2 += v0 * Jm1 - v1 * Jm0;
        u  += v0 * Jm0 + v1 * Jm1 + v2 * Jm2;
        deg += 1.0f; s0 += v0; s1 += v1; s2 += v2;
        const float vv = v0 * v0 + v1 * v1 + v2 * v2;
        G += vv;
        c00 += vv - v0 * v0; c01 -= v0 * v1; c02 -= v0 * v2;
        c11 += vv - v1 * v1; c12 -= v1 * v2; c22 += vv - v2 * v2;
    }

    const float LJ0 = 2.0f * (deg * Jn0 - nb0);
    const float LJ1 = 2.0f * (deg * Jn1 - nb1);
    const float LJ2 = 2.0f * (deg * Jn2 - nb2);
    const float B0 = T0 + s2 * Jn1 - s1 * Jn2;
    const float B1 = T1 - s2 * Jn0 + s0 * Jn2;
    const float B2 = T2 + s1 * Jn0 - s0 * Jn1;
    const float y = u - (s0 * Jn0 + s1 * Jn1 + s2 * Jn2);
    // Cholesky C = L L^T,  Z = L^{-1} BTJ
    const float l00 = sqrtf(c00);
    const float il00 = 1.0f / l00;
    const float l10 = c01 * il00, l20 = c02 * il00;
    const float l11 = sqrtf(c11 - l10 * l10);
    const float il11 = 1.0f / l11;
    const float l21 = (c12 - l20 * l10) * il11;
    const float l22 = sqrtf(c22 - l20 * l20 - l21 * l21);
    const float il22 = 1.0f / l22;
    const float Z0 = B0 * il00;
    const float Z1 = (B1 - l10 * Z0) * il11;
    const float Z2 = (B2 - l20 * Z0 - l21 * Z1) * il22;
    const float Ginv = (G < 1e-6f) ? 0.0f : 1.0f / G;

    float* P = g_pan + ((size_t)b * N_NODES + n) * 1024 + c;
    P[0]       = Z0;  P[128] = Z1;  P[256] = Z2;  P[384] = y;
    P[512]     = LJ0; P[640] = LJ1; P[768] = LJ2;
    P[896]     = -(WPRIME * Ginv) * y;
}

// ---------------- K2b: split-K GEMM, Rm += sum_n A_n^T B_n ----------------
#define GTILE 128
#define GNIT  (GTILE / 2)

__device__ __forceinline__ void cp_async16(void* dst_smem, const void* src) {
    uint32_t d = (uint32_t)__cvta_generic_to_shared(dst_smem);
    asm volatile("cp.async.cg.shared.global [%0], [%1], 16;" :: "r"(d), "l"(src));
}
__device__ __forceinline__ void cp_commit() { asm volatile("cp.async.commit_group;"); }
template<int NN> __device__ __forceinline__ void cp_wait() {
    asm volatile("cp.async.wait_group %0;" :: "n"(NN));
}

__global__ void __launch_bounds__(256, 2)
gemm_kernel(const float* __restrict__ J) {
    __shared__ __align__(16) float sJ[2][6 * 128];
    __shared__ __align__(16) float sP[2][16 * 128];

    const int b = blockIdx.y;
    const int base = blockIdx.x * GTILE;
    const int t = threadIdx.x;
    const int ty = t >> 4, tx = t & 15;
    const float* Jb = J + (size_t)b * N_NODES * 3 * D;
    const float* Pb = g_pan + (size_t)b * N_NODES * 1024;

    float acc[8][8];
#pragma unroll
    for (int i = 0; i < 8; i++)
#pragma unroll
        for (int j = 0; j < 8; j++) acc[i][j] = 0.0f;

    // stage tile for node pair `it` into buffer `buf`
    auto issue = [&](int it, int buf) {
        const int n0 = base + it * 2;
        const float* jsrc = Jb + (size_t)(3 * n0) * D;   // 6 rows = 768 floats
        const float* psrc = Pb + (size_t)n0 * 1024;      // 16 rows = 2048 floats
        if (t < 192) cp_async16(&sJ[buf][t * 4], jsrc + t * 4);
        cp_async16(&sP[buf][t * 4], psrc + t * 4);
        cp_async16(&sP[buf][(t + 256) * 4], psrc + (t + 256) * 4);
    };

    issue(0, 0); cp_commit();

    for (int it = 0; it < GNIT; ++it) {
        const int buf = it & 1;
        if (it + 1 < GNIT) { issue(it + 1, buf ^ 1); cp_commit(); cp_wait<1>(); }
        else cp_wait<0>();
        __syncthreads();

        const float* sj = sJ[buf];
        const float* sp = sP[buf];

#pragma unroll
        for (int g = 0; g < 2; ++g) {
            const float* pg = sp + g * 8 * 128;
            float av[8], bv[8];

#define LD8(dst, ptr) { float4 _a = *(const float4*)(ptr); float4 _b = *(const float4*)((ptr) + 4); \
    dst[0]=_a.x; dst[1]=_a.y; dst[2]=_a.z; dst[3]=_a.w; dst[4]=_b.x; dst[5]=_b.y; dst[6]=_b.z; dst[7]=_b.w; }

            // ranks 0..2:  J_k (a)  x  LJ_k (b)
#pragma unroll
            for (int k = 0; k < 3; ++k) {
                LD8(av, sj + (3 * g + k) * 128 + ty * 8);
                LD8(bv, pg + (4 + k) * 128 + tx * 8);
#pragma unroll
                for (int i = 0; i < 8; i++)
#pragma unroll
                    for (int j = 0; j < 8; j++) acc[i][j] += av[i] * bv[j];
            }
            // ranks 3..5:  Z_k (a)  x  -Z_k (b)
#pragma unroll
            for (int k = 0; k < 3; ++k) {
                LD8(av, pg + k * 128 + ty * 8);
                LD8(bv, pg + k * 128 + tx * 8);
#pragma unroll
                for (int i = 0; i < 8; i++)
#pragma unroll
                    for (int j = 0; j < 8; j++) acc[i][j] -= av[i] * bv[j];
            }
            // rank 6:  y (a)  x  gy (b)
            LD8(av, pg + 3 * 128 + ty * 8);
            LD8(bv, pg + 7 * 128 + tx * 8);
#pragma unroll
            for (int i = 0; i < 8; i++)
#pragma unroll
                for (int j = 0; j < 8; j++) acc[i][j] += av[i] * bv[j];
#undef LD8
        }
        __syncthreads();
    }

    float* Rm = g_Rm + (size_t)b * D * D;
#pragma unroll
    for (int i = 0; i < 8; i++)
#pragma unroll
        for (int j = 0; j < 8; j++)
            atomicAdd(&Rm[(ty * 8 + i) * D + (tx * 8 + j)], acc[i][j]);
}

// ---------------- block reductions (128 threads) ----------------
__device__ __forceinline__ float blockReduceSum(float v, float* red) {
#pragma unroll
    for (int off = 16; off > 0; off >>= 1) v += __shfl_down_sync(0xffffffffu, v, off);
    if ((threadIdx.x & 31) == 0) red[threadIdx.x >> 5] = v;
    __syncthreads();
    if (threadIdx.x == 0) red[0] = red[0] + red[1] + red[2] + red[3];
    __syncthreads();
    const float r = red[0];
    __syncthreads();
    return r;
}
__device__ __forceinline__ float blockReduceMin(float v, float* red) {
#pragma unroll
    for (int off = 16; off > 0; off >>= 1) v = fminf(v, __shfl_down_sync(0xffffffffu, v, off));
    if ((threadIdx.x & 31) == 0) red[threadIdx.x >> 5] = v;
    __syncthreads();
    if (threadIdx.x == 0) red[0] = fminf(fminf(red[0], red[1]), fminf(red[2], red[3]));
    __syncthreads();
    const float r = red[0];
    __syncthreads();
    return r;
}
__device__ __forceinline__ float blockReduceMax(float v, float* red) {
#pragma unroll
    for (int off = 16; off > 0; off >>= 1) v = fmaxf(v, __shfl_down_sync(0xffffffffu, v, off));
    if ((threadIdx.x & 31) == 0) red[threadIdx.x >> 5] = v;
    __syncthreads();
    if (threadIdx.x == 0) red[0] = fmaxf(fmaxf(red[0], red[1]), fmaxf(red[2], red[3]));
    __syncthreads();
    const float r = red[0];
    __syncthreads();
    return r;
}

// ---------------- K3: Householder tridiagonalization + Sturm bisection ----------------
#define ASTR 132   // row stride: multiple of 4 (float4-aligned), 528B%128B=16 -> conflict-free LDS.128
#define SMEM_EIG ((128 * ASTR + 5 * 128 + 32) * 4)

__global__ void eigen_kernel() {
    extern __shared__ float sm[];
    float* A   = sm;                  // 128 x ASTR
    float* uu  = A + 128 * ASTR;      // 128
    float* qq  = uu + 128;            // 128
    float* dd  = qq + 128;            // 128
    float* ee  = dd + 128;            // 128
    float* e2  = ee + 128;            // 128
    float* red = e2 + 128;            // 32

    const int b = blockIdx.x;
    const int t = threadIdx.x;
    const float* R = g_Rm + (size_t)b * D * D;

    // load + symmetrize
#pragma unroll 4
    for (int i = 0; i < 128; i++)
        A[i * ASTR + t] = 0.5f * (R[i * 128 + t] + R[t * 128 + i]);
    __syncthreads();

    // Householder reduction to tridiagonal, float4 inner loops
    for (int k = 0; k < 126; k++) {
        const float xi = (t > k) ? A[t * ASTR + k] : 0.0f;
        const float sig = blockReduceSum(xi * xi, red);
        const float x0 = A[(k + 1) * ASTR + k];
        const float nrm = sqrtf(sig);
        const float alpha = (x0 >= 0.0f) ? -nrm : nrm;
        const float H = sig - alpha * x0;
        if (t == 0) ee[k + 1] = alpha;
        const float ui = (t > k) ? (xi - ((t == k + 1) ? alpha : 0.0f)) : 0.0f;
        uu[t] = ui;
        __syncthreads();
        if (H > 1e-32f) {                      // block-uniform condition
            const float invH = 1.0f / H;
            const int j0 = (k + 1) & ~3;       // u,q are exactly 0 for j<=k -> safe
            const int m = (128 - j0) >> 2;
            float p = 0.0f;
            if (t > k) {
                const float4* Ar4 = (const float4*)(A + t * ASTR + j0);
                const float4* U4  = (const float4*)(uu + j0);
#pragma unroll 4
                for (int q = 0; q < m; q++) {
                    const float4 a = Ar4[q], u4 = U4[q];
                    p += a.x * u4.x + a.y * u4.y + a.z * u4.z + a.w * u4.w;
                }
                p *= invH;
            }
            const float Ks = blockReduceSum(ui * p, red);
            const float Kc = Ks * 0.5f * invH;
            qq[t] = p - Kc * ui;               // 0 for t<=k (p guarded, ui=0)
            __syncthreads();
            if (t > k) {
                float4* Ar4 = (float4*)(A + t * ASTR + j0);
                const float4* U4 = (const float4*)(uu + j0);
                const float4* Q4 = (const float4*)(qq + j0);
                const float uif = ui, qif = qq[t];
#pragma unroll 4
                for (int q = 0; q < m; q++) {
                    float4 a = Ar4[q];
                    const float4 u4 = U4[q], q4 = Q4[q];
                    a.x -= uif * q4.x + qif * u4.x;
                    a.y -= uif * q4.y + qif * u4.y;
                    a.z -= uif * q4.z + qif * u4.z;
                    a.w -= uif * q4.w + qif * u4.w;
                    Ar4[q] = a;
                }
            }
        }
        __syncthreads();
    }

    dd[t] = A[t * ASTR + t];
    if (t == 0) { ee[0] = 0.0f; ee[127] = A[127 * ASTR + 126]; }
    __syncthreads();
    e2[t] = ee[t] * ee[t];
    const float rad = fabsf(ee[t]) + ((t < 127) ? fabsf(ee[t + 1]) : 0.0f);
    const float gl = blockReduceMin(dd[t] - rad, red);
    const float gu = blockReduceMax(dd[t] + rad, red);
    __syncthreads();

    // bisection: thread t finds the t-th smallest eigenvalue
    const float pivmin = fmaxf(1e-12f * fmaxf(fabsf(gl), fabsf(gu)), 1e-36f);
    float lo = gl, hi = gu;
    for (int iter = 0; iter < 36; ++iter) {
        const float mid = 0.5f * (lo + hi);
        int cnt = 0;
        float q = dd[0] - mid;
        if (q < 0.0f) cnt++;
#pragma unroll 4
        for (int i = 1; i < 128; i++) {
            if (fabsf(q) < pivmin) q = -pivmin;
            q = dd[i] - mid - __fdividef(e2[i], q);
            if (q < 0.0f) cnt++;
        }
        if (cnt > t) hi = mid; else lo = mid;
    }
    const float lam = 0.5f * (lo + hi);
    const float v = (lam > 0.0f) ? sqrtf(lam) : 0.0f;
    const float s = blockReduceSum(v, red);
    if (t == 0) g_partial[b] = s;
}

// ---------------- K4: mean over batch ----------------
__global__ void finalize_kernel(float* out) {
    out[0] = 0.25f * (g_partial[0] + g_partial[1] + g_partial[2] + g_partial[3]);
}

// ---------------- launch ----------------
extern "C" void kernel_launch(void* const* d_in, const int* in_sizes, int n_in,
                              void* d_out, int out_size) {
    const float* x  = (const float*)d_in[0];
    const float* J  = (const float*)d_in[1];
    const int*   ei = (const int*)d_in[2];     // [2, E] int32, e0 sorted
    const int E = in_sizes[2] / 2;
    float* out = (float*)d_out;

    cudaFuncSetAttribute(eigen_kernel,
                         cudaFuncAttributeMaxDynamicSharedMemorySize, SMEM_EIG);

    zero_kernel<<<64, 1024>>>();
    rowptr_kernel<<<(N_NODES + 1 + 255) / 256, 256>>>(ei, E);

    dim3 gbuild(N_NODES / 2, BATCH);
    build_kernel<<<gbuild, 256>>>(x, J, ei + E);

    dim3 ggemm(N_NODES / GTILE, BATCH);
    gemm_kernel<<<ggemm, 256>>>(J);

    eigen_kernel<<<BATCH, 128, SMEM_EIG>>>();
    finalize_kernel<<<1, 1>>>(out);
}

// round 3
// speedup vs baseline: 1.6753x; 1.3210x over previous
#include <cuda_runtime.h>
#include <math.h>
#include <stdint.h>

#define N_NODES 16384
#define D 128
#define BATCH 4
#define WPRIME (0.05f/1.05f)

#define KS 64                    // split-K factor
#define CHUNK (N_NODES / KS)     // 256 nodes per block
#define STAGES 4
#define SROW 136                 // smem row stride (floats): (136k+m)%32=(8k+m)%32 -> conflict-free frags

// ---------------- device scratch (no allocations allowed) ----------------
__device__ float g_Rm[BATCH * D * D];
__device__ float g_Rp[(size_t)BATCH * KS * D * D];
__device__ int   g_rowptr[N_NODES + 1];
__device__ float g_partial[BATCH];
// per node 16 rows x 128: A=[J0,J1,J2,Z0,Z1,Z2,y,0]  B=[LJ0,LJ1,LJ2,-Z0,-Z1,-Z2,gy,0]
__device__ float g_pan[(size_t)BATCH * N_NODES * 2048];

// ---------------- K1: CSR row pointers (e0 sorted ascending) ----------------
__global__ void rowptr_kernel(const int* __restrict__ e0, int E) {
    int n = blockIdx.x * blockDim.x + threadIdx.x;
    if (n > N_NODES) return;
    int lo = 0, hi = E;
    while (lo < hi) {
        int mid = (lo + hi) >> 1;
        if (e0[mid] < n) lo = mid + 1; else hi = mid;
    }
    g_rowptr[n] = lo;
}

// ---------------- K2a: build per-node A|B panels ----------------
__global__ void __launch_bounds__(256)
build_kernel(const float* __restrict__ x, const float* __restrict__ J,
             const int* __restrict__ e1arr) {
    const int b = blockIdx.y;
    const int n = blockIdx.x * 2 + (threadIdx.x >> 7);
    const int c = threadIdx.x & 127;

    const float* xb = x + (size_t)b * N_NODES * 3;
    const float* Jb = J + (size_t)b * N_NODES * 3 * D;

    const float* Jn = Jb + (size_t)(3 * n) * D + c;
    const float Jn0 = Jn[0], Jn1 = Jn[D], Jn2 = Jn[2 * D];
    const float xn0 = xb[3 * n], xn1 = xb[3 * n + 1], xn2 = xb[3 * n + 2];

    float nb0 = 0.f, nb1 = 0.f, nb2 = 0.f;
    float T0 = 0.f, T1 = 0.f, T2 = 0.f, u = 0.f;
    float deg = 0.f, s0 = 0.f, s1 = 0.f, s2 = 0.f, G = 0.f;
    float c00 = 0.f, c01 = 0.f, c02 = 0.f, c11 = 0.f, c12 = 0.f, c22 = 0.f;

    const int eBeg = g_rowptr[n], eEnd = g_rowptr[n + 1];
#pragma unroll 2
    for (int e = eBeg; e < eEnd; ++e) {
        const int m = e1arr[e];
        const float v0 = xn0 - xb[3 * m];
        const float v1 = xn1 - xb[3 * m + 1];
        const float v2 = xn2 - xb[3 * m + 2];
        const float* Jm = Jb + (size_t)(3 * m) * D + c;
        const float Jm0 = Jm[0], Jm1 = Jm[D], Jm2 = Jm[2 * D];
        nb0 += Jm0; nb1 += Jm1; nb2 += Jm2;
        T0 += v1 * Jm2 - v2 * Jm1;
        T1 += v2 * Jm0 - v0 * Jm2;
        T2 += v0 * Jm1 - v1 * Jm0;
        u  += v0 * Jm0 + v1 * Jm1 + v2 * Jm2;
        deg += 1.0f; s0 += v0; s1 += v1; s2 += v2;
        const float vv = v0 * v0 + v1 * v1 + v2 * v2;
        G += vv;
        c00 += vv - v0 * v0; c01 -= v0 * v1; c02 -= v0 * v2;
        c11 += vv - v1 * v1; c12 -= v1 * v2; c22 += vv - v2 * v2;
    }

    const float LJ0 = 2.0f * (deg * Jn0 - nb0);
    const float LJ1 = 2.0f * (deg * Jn1 - nb1);
    const float LJ2 = 2.0f * (deg * Jn2 - nb2);
    const float B0 = T0 + s2 * Jn1 - s1 * Jn2;
    const float B1 = T1 - s2 * Jn0 + s0 * Jn2;
    const float B2 = T2 + s1 * Jn0 - s0 * Jn1;
    const float y = u - (s0 * Jn0 + s1 * Jn1 + s2 * Jn2);
    // Cholesky C = L L^T, Z = L^{-1} BTJ
    const float l00 = sqrtf(c00);
    const float il00 = 1.0f / l00;
    const float l10 = c01 * il00, l20 = c02 * il00;
    const float l11 = sqrtf(c11 - l10 * l10);
    const float il11 = 1.0f / l11;
    const float l21 = (c12 - l20 * l10) * il11;
    const float l22 = sqrtf(c22 - l20 * l20 - l21 * l21);
    const float il22 = 1.0f / l22;
    const float Z0 = B0 * il00;
    const float Z1 = (B1 - l10 * Z0) * il11;
    const float Z2 = (B2 - l20 * Z0 - l21 * Z1) * il22;
    const float Ginv = (G < 1e-6f) ? 0.0f : 1.0f / G;

    float* P = g_pan + ((size_t)b * N_NODES + n) * 2048 + c;
    // A panel rows 0..7
    P[0*128] = Jn0;  P[1*128] = Jn1;  P[2*128] = Jn2;
    P[3*128] = Z0;   P[4*128] = Z1;   P[5*128] = Z2;
    P[6*128] = y;    P[7*128] = 0.0f;
    // B panel rows 8..15
    P[8*128]  = LJ0; P[9*128]  = LJ1; P[10*128] = LJ2;
    P[11*128] = -Z0; P[12*128] = -Z1; P[13*128] = -Z2;
    P[14*128] = -(WPRIME * Ginv) * y; P[15*128] = 0.0f;
}

// ---------------- K2b: TF32 tensor-core split-K GEMM ----------------
__device__ __forceinline__ void cp_async16(void* dst_smem, const void* src) {
    uint32_t d = (uint32_t)__cvta_generic_to_shared(dst_smem);
    asm volatile("cp.async.cg.shared.global [%0], [%1], 16;" :: "r"(d), "l"(src));
}
__device__ __forceinline__ void cp_commit() { asm volatile("cp.async.commit_group;"); }
template<int NN> __device__ __forceinline__ void cp_wait() {
    asm volatile("cp.async.wait_group %0;" :: "n"(NN));
}
__device__ __forceinline__ uint32_t tf32c(float f) {
    uint32_t u; asm("cvt.rna.tf32.f32 %0, %1;" : "=r"(u) : "f"(f)); return u;
}
__device__ __forceinline__ void mma_tf32(float* d, uint32_t a0, uint32_t a1,
                                         uint32_t a2, uint32_t a3,
                                         uint32_t b0, uint32_t b1) {
    asm volatile(
        "mma.sync.aligned.m16n8k8.row.col.f32.tf32.tf32.f32 "
        "{%0,%1,%2,%3}, {%4,%5,%6,%7}, {%8,%9}, {%0,%1,%2,%3};"
        : "+f"(d[0]), "+f"(d[1]), "+f"(d[2]), "+f"(d[3])
        : "r"(a0), "r"(a1), "r"(a2), "r"(a3), "r"(b0), "r"(b1));
}

__global__ void __launch_bounds__(256, 2)
gemm_kernel() {
    __shared__ __align__(16) float sm[STAGES][16][SROW];

    const int b = blockIdx.y, ks = blockIdx.x;
    const int t = threadIdx.x;
    const int wid = t >> 5, lane = t & 31;
    const int wm = (wid >> 2) * 64;   // warp m offset: 0/64
    const int wn = (wid & 3) * 32;    // warp n offset: 0/32/64/96
    const int r0 = lane >> 2, kc = lane & 3;

    const float* Pb = g_pan + ((size_t)b * N_NODES + (size_t)ks * CHUNK) * 2048;

    float acc[4][4][4];
#pragma unroll
    for (int i = 0; i < 4; i++)
#pragma unroll
        for (int j = 0; j < 4; j++)
#pragma unroll
            for (int r = 0; r < 4; r++) acc[i][j][r] = 0.0f;

    auto issue = [&](int it) {
        const int stg = it & (STAGES - 1);
        const float* src = Pb + (size_t)it * 2048;
        int ch = t;          // chunk 0..511 of 16B
        cp_async16(&sm[stg][ch >> 5][(ch & 31) * 4], src + ch * 4);
        ch = t + 256;
        cp_async16(&sm[stg][ch >> 5][(ch & 31) * 4], src + ch * 4);
    };

    for (int s = 0; s < STAGES - 1; s++) { issue(s); cp_commit(); }

    for (int it = 0; it < CHUNK; ++it) {
        const int stg = it & (STAGES - 1);
        if (it + STAGES - 1 < CHUNK) issue(it + STAGES - 1);
        cp_commit();                    // keep 1 group/iter accounting (may be empty)
        cp_wait<STAGES - 1>();          // stage `it` complete
        __syncthreads();

        const float* SA = &sm[stg][0][0];
        const float* SB = SA + 8 * SROW;

        uint32_t bb[4][2];
#pragma unroll
        for (int nt = 0; nt < 4; nt++) {
            const int n = wn + nt * 8 + r0;
            bb[nt][0] = tf32c(SB[kc * SROW + n]);
            bb[nt][1] = tf32c(SB[(kc + 4) * SROW + n]);
        }
#pragma unroll
        for (int mt = 0; mt < 4; mt++) {
            const int m = wm + mt * 16 + r0;
            const uint32_t a0 = tf32c(SA[kc * SROW + m]);
            const uint32_t a1 = tf32c(SA[kc * SROW + m + 8]);
            const uint32_t a2 = tf32c(SA[(kc + 4) * SROW + m]);
            const uint32_t a3 = tf32c(SA[(kc + 4) * SROW + m + 8]);
#pragma unroll
            for (int nt = 0; nt < 4; nt++)
                mma_tf32(acc[mt][nt], a0, a1, a2, a3, bb[nt][0], bb[nt][1]);
        }
        __syncthreads();
    }

    float* out = g_Rp + (((size_t)b * KS + ks) << 14);
#pragma unroll
    for (int mt = 0; mt < 4; mt++) {
        const int m = wm + mt * 16 + r0;
#pragma unroll
        for (int nt = 0; nt < 4; nt++) {
            const int n = wn + nt * 8 + 2 * kc;
            *(float2*)&out[m * 128 + n]       = make_float2(acc[mt][nt][0], acc[mt][nt][1]);
            *(float2*)&out[(m + 8) * 128 + n] = make_float2(acc[mt][nt][2], acc[mt][nt][3]);
        }
    }
}

// ---------------- K2c: reduce split-K partials ----------------
__global__ void reduce_kernel() {
    const int idx = blockIdx.x * 256 + threadIdx.x;   // 0..65535
    const int b = idx >> 14, e = idx & 16383;
    const float* p = g_Rp + (((size_t)b * KS) << 14) + e;
    float s = 0.0f;
#pragma unroll 8
    for (int k = 0; k < KS; k++) s += p[(size_t)k << 14];
    g_Rm[idx] = s;
}

// ---------------- block reductions (128 threads) ----------------
__device__ __forceinline__ float blockReduceSum(float v, float* red) {
#pragma unroll
    for (int off = 16; off > 0; off >>= 1) v += __shfl_down_sync(0xffffffffu, v, off);
    if ((threadIdx.x & 31) == 0) red[threadIdx.x >> 5] = v;
    __syncthreads();
    if (threadIdx.x == 0) red[0] = red[0] + red[1] + red[2] + red[3];
    __syncthreads();
    const float r = red[0];
    __syncthreads();
    return r;
}
__device__ __forceinline__ float blockReduceMin(float v, float* red) {
#pragma unroll
    for (int off = 16; off > 0; off >>= 1) v = fminf(v, __shfl_down_sync(0xffffffffu, v, off));
    if ((threadIdx.x & 31) == 0) red[threadIdx.x >> 5] = v;
    __syncthreads();
    if (threadIdx.x == 0) red[0] = fminf(fminf(red[0], red[1]), fminf(red[2], red[3]));
    __syncthreads();
    const float r = red[0];
    __syncthreads();
    return r;
}
__device__ __forceinline__ float blockReduceMax(float v, float* red) {
#pragma unroll
    for (int off = 16; off > 0; off >>= 1) v = fmaxf(v, __shfl_down_sync(0xffffffffu, v, off));
    if ((threadIdx.x & 31) == 0) red[threadIdx.x >> 5] = v;
    __syncthreads();
    if (threadIdx.x == 0) red[0] = fmaxf(fmaxf(red[0], red[1]), fmaxf(red[2], red[3]));
    __syncthreads();
    const float r = red[0];
    __syncthreads();
    return r;
}

// ---------------- K3: Householder tridiagonalization + Sturm bisection ----------------
#define ASTR 132
#define SMEM_EIG ((128 * ASTR + 5 * 128 + 32) * 4)

__global__ void eigen_kernel() {
    extern __shared__ float smE[];
    float* A   = smE;
    float* uu  = A + 128 * ASTR;
    float* qq  = uu + 128;
    float* dd  = qq + 128;
    float* ee  = dd + 128;
    float* e2  = ee + 128;
    float* red = e2 + 128;

    const int b = blockIdx.x;
    const int t = threadIdx.x;
    const float* R = g_Rm + (size_t)b * D * D;

#pragma unroll 4
    for (int i = 0; i < 128; i++)
        A[i * ASTR + t] = 0.5f * (R[i * 128 + t] + R[t * 128 + i]);
    __syncthreads();

    for (int k = 0; k < 126; k++) {
        const float xi = (t > k) ? A[t * ASTR + k] : 0.0f;
        const float sig = blockReduceSum(xi * xi, red);
        const float x0 = A[(k + 1) * ASTR + k];
        const float nrm = sqrtf(sig);
        const float alpha = (x0 >= 0.0f) ? -nrm : nrm;
        const float H = sig - alpha * x0;
        if (t == 0) ee[k + 1] = alpha;
        const float ui = (t > k) ? (xi - ((t == k + 1) ? alpha : 0.0f)) : 0.0f;
        uu[t] = ui;
        __syncthreads();
        if (H > 1e-32f) {
            const float invH = 1.0f / H;
            const int j0 = (k + 1) & ~3;        // u,q are exactly 0 for j<=k
            const int m = (128 - j0) >> 2;
            float p = 0.0f;
            if (t > k) {
                const float4* Ar4 = (const float4*)(A + t * ASTR + j0);
                const float4* U4  = (const float4*)(uu + j0);
                float pa[4] = {0.f, 0.f, 0.f, 0.f};   // break the FMA chain
#pragma unroll 4
                for (int q = 0; q < m; q++) {
                    const float4 a = Ar4[q], u4 = U4[q];
                    pa[q & 3] += a.x * u4.x + a.y * u4.y + a.z * u4.z + a.w * u4.w;
                }
                p = ((pa[0] + pa[1]) + (pa[2] + pa[3])) * invH;
            }
            const float Ks = blockReduceSum(ui * p, red);
            const float Kc = Ks * 0.5f * invH;
            qq[t] = p - Kc * ui;
            __syncthreads();
            if (t > k) {
                float4* Ar4 = (float4*)(A + t * ASTR + j0);
                const float4* U4 = (const float4*)(uu + j0);
                const float4* Q4 = (const float4*)(qq + j0);
                const float uif = ui, qif = qq[t];
#pragma unroll 4
                for (int q = 0; q < m; q++) {
                    float4 a = Ar4[q];
                    const float4 u4 = U4[q], q4 = Q4[q];
                    a.x -= uif * q4.x + qif * u4.x;
                    a.y -= uif * q4.y + qif * u4.y;
                    a.z -= uif * q4.z + qif * u4.z;
                    a.w -= uif * q4.w + qif * u4.w;
                    Ar4[q] = a;
                }
            }
        }
        __syncthreads();
    }

    dd[t] = A[t * ASTR + t];
    if (t == 0) { ee[0] = 0.0f; ee[127] = A[127 * ASTR + 126]; }
    __syncthreads();
    e2[t] = ee[t] * ee[t];
    const float rad = fabsf(ee[t]) + ((t < 127) ? fabsf(ee[t + 1]) : 0.0f);
    const float gl = blockReduceMin(dd[t] - rad, red);
    const float gu = blockReduceMax(dd[t] + rad, red);
    __syncthreads();

    const float pivmin = fmaxf(1e-12f * fmaxf(fabsf(gl), fabsf(gu)), 1e-36f);
    float lo = gl, hi = gu;
    for (int iter = 0; iter < 36; ++iter) {
        const float mid = 0.5f * (lo + hi);
        int cnt = 0;
        float q = dd[0] - mid;
        if (q < 0.0f) cnt++;
#pragma unroll 4
        for (int i = 1; i < 128; i++) {
            if (fabsf(q) < pivmin) q = -pivmin;
            q = dd[i] - mid - __fdividef(e2[i], q);
            if (q < 0.0f) cnt++;
        }
        if (cnt > t) hi = mid; else lo = mid;
    }
    const float lam = 0.5f * (lo + hi);
    const float v = (lam > 0.0f) ? sqrtf(lam) : 0.0f;
    const float s = blockReduceSum(v, red);
    if (t == 0) g_partial[b] = s;
}

// ---------------- K4: mean over batch ----------------
__global__ void finalize_kernel(float* out) {
    out[0] = 0.25f * (g_partial[0] + g_partial[1] + g_partial[2] + g_partial[3]);
}

// ---------------- launch ----------------
extern "C" void kernel_launch(void* const* d_in, const int* in_sizes, int n_in,
                              void* d_out, int out_size) {
    const float* x  = (const float*)d_in[0];
    const float* J  = (const float*)d_in[1];
    const int*   ei = (const int*)d_in[2];     // [2, E] int32, e0 sorted
    const int E = in_sizes[2] / 2;
    float* out = (float*)d_out;

    cudaFuncSetAttribute(eigen_kernel,
                         cudaFuncAttributeMaxDynamicSharedMemorySize, SMEM_EIG);

    rowptr_kernel<<<(N_NODES + 1 + 255) / 256, 256>>>(ei, E);

    dim3 gbuild(N_NODES / 2, BATCH);
    build_kernel<<<gbuild, 256>>>(x, J, ei + E);

    dim3 ggemm(KS, BATCH);
    gemm_kernel<<<ggemm, 256>>>();
    reduce_kernel<<<BATCH * D * D / 256, 256>>>();

    eigen_kernel<<<BATCH, 128, SMEM_EIG>>>();
    finalize_kernel<<<1, 1>>>(out);
}